// round 1
// baseline (speedup 1.0000x reference)
#include <cuda_runtime.h>

#define NODE_DIM 128
#define EDGE_DIM 64
#define MSG_DIM  128
#define H1 32
#define H2 64
#define MAXN 50000

// Scratch: per-node precomputed projections
// P[n][0:32]  = nf[n] @ We1[0:128]   + be1   (src contribution, bias folded)
// P[n][32:64] = nf[n] @ We1[128:256]         (dst contribution)
// P[n][64:128]= nf[n] @ Wn1[0:128]   + bn1   (node-mlp dst contribution)
__device__ float g_P[MAXN * 128];

// ---------------------------------------------------------------------------
// Precompute kernel: 8 nodes per block, 128 threads (thread j = output col j).
// Also initializes out = node_features.
// ---------------------------------------------------------------------------
__global__ void __launch_bounds__(128) precompute_kernel(
    const float* __restrict__ nf,
    const float* __restrict__ We1,
    const float* __restrict__ be1,
    const float* __restrict__ Wn1,
    const float* __restrict__ bn1,
    float* __restrict__ out, int Nn)
{
    __shared__ float nfs[8][NODE_DIM];
    const int nb  = blockIdx.x * 8;
    const int tid = threadIdx.x;

    #pragma unroll
    for (int i = 0; i < 8; i++) {
        int n = nb + i;
        if (n < Nn) {
            float v = nf[n * NODE_DIM + tid];
            nfs[i][tid] = v;
            out[n * NODE_DIM + tid] = v;   // output init: node_features
        } else {
            nfs[i][tid] = 0.f;
        }
    }
    __syncthreads();

    const int j = tid;
    const float* wcol;
    int stride;
    float bias;
    if (j < 32)      { wcol = We1 + j;                 stride = H1; bias = be1[j]; }
    else if (j < 64) { wcol = We1 + 128 * H1 + (j-32); stride = H1; bias = 0.f; }
    else             { wcol = Wn1 + (j - 64);          stride = H2; bias = bn1[j-64]; }

    float acc[8];
    #pragma unroll
    for (int i = 0; i < 8; i++) acc[i] = bias;

    #pragma unroll 4
    for (int k = 0; k < NODE_DIM; k += 2) {
        float w0 = wcol[k * stride];
        float w1 = wcol[(k + 1) * stride];
        #pragma unroll
        for (int i = 0; i < 8; i++) {
            float2 v = *(const float2*)&nfs[i][k];   // LDS.64 broadcast
            acc[i] += v.x * w0;
            acc[i] += v.y * w1;
        }
    }

    #pragma unroll
    for (int i = 0; i < 8; i++) {
        int n = nb + i;
        if (n < Nn) g_P[n * 128 + tid] = acc[i];
    }
}

// ---------------------------------------------------------------------------
// Edge kernel: 1 warp handles 4 edges simultaneously (weight LDS amortized 4x).
// Weights staged in dynamic shared memory (~89 KB). Grid-stride over edges.
// ---------------------------------------------------------------------------
#define TPB 256
#define WPB (TPB / 32)
#define EPW 4

__global__ void __launch_bounds__(TPB) edge_kernel(
    const float* __restrict__ ef,
    const int*   __restrict__ eidx,
    const float* __restrict__ We1,
    const float* __restrict__ We2,
    const float* __restrict__ be2,
    const float* __restrict__ Wn1,
    const float* __restrict__ Wn2,
    const float* __restrict__ bn2,
    float* __restrict__ out, int E)
{
    extern __shared__ float smem[];
    float* We1s = smem;                 // [64][32]   edge rows of We1
    float* We2s = We1s + 64 * 32;       // [32][128]
    float* Wn1s = We2s + 32 * 128;      // [128][64]  msg rows of Wn1
    float* Wn2s = Wn1s + 128 * 64;      // [64][128]
    float* be2s = Wn2s + 64 * 128;      // [128]
    float* bn2s = be2s + 128;           // [128]

    const int tid = threadIdx.x;
    for (int i = tid; i < 64 * 32;  i += TPB) We1s[i] = We1[256 * 32 + i];
    for (int i = tid; i < 32 * 128; i += TPB) We2s[i] = We2[i];
    for (int i = tid; i < 128 * 64; i += TPB) Wn1s[i] = Wn1[128 * 64 + i];
    for (int i = tid; i < 64 * 128; i += TPB) Wn2s[i] = Wn2[i];
    if (tid < 128) { be2s[tid] = be2[tid]; bn2s[tid] = bn2[tid]; }
    __syncthreads();

    const int lane  = tid & 31;
    const int gwarp = blockIdx.x * WPB + (tid >> 5);
    const int nwarp = gridDim.x * WPB;
    const unsigned FULL = 0xFFFFFFFFu;

    for (int base = gwarp * EPW; base < E; base += nwarp * EPW) {
        int dst[EPW];
        bool valid[EPW];
        float ef0[EPW], ef1[EPW], h[EPW], p2a[EPW], p2b[EPW];

        #pragma unroll
        for (int i = 0; i < EPW; i++) {
            int e = base + i;
            valid[i] = (e < E);
            if (!valid[i]) e = 0;
            int s  = eidx[e];
            dst[i] = eidx[E + e];
            ef0[i] = ef[e * EDGE_DIM + lane];
            ef1[i] = ef[e * EDGE_DIM + 32 + lane];
            // pre1 (be1 folded into src slice of P)
            h[i]   = g_P[s * 128 + lane] + g_P[dst[i] * 128 + 32 + lane];
            // pre2 (bn1 folded)
            p2a[i] = g_P[dst[i] * 128 + 64 + lane];
            p2b[i] = g_P[dst[i] * 128 + 96 + lane];
        }

        // ---- Layer 1: h[j=lane] = relu(pre1 + ef(64) @ We1_e[64][32]) ----
        #pragma unroll
        for (int k = 0; k < 32; k++) {
            float w = We1s[k * 32 + lane];
            #pragma unroll
            for (int i = 0; i < EPW; i++)
                h[i] += __shfl_sync(FULL, ef0[i], k) * w;
        }
        #pragma unroll
        for (int k = 0; k < 32; k++) {
            float w = We1s[(32 + k) * 32 + lane];
            #pragma unroll
            for (int i = 0; i < EPW; i++)
                h[i] += __shfl_sync(FULL, ef1[i], k) * w;
        }
        #pragma unroll
        for (int i = 0; i < EPW; i++) h[i] = fmaxf(h[i], 0.f);

        // ---- Layer 2: em[r*32+lane] = relu(be2 + h(32) @ We2[32][128]) ----
        float em[4][EPW];
        #pragma unroll
        for (int r = 0; r < 4; r++)
            #pragma unroll
            for (int i = 0; i < EPW; i++) em[r][i] = be2s[r * 32 + lane];
        #pragma unroll
        for (int k = 0; k < 32; k++) {
            float hk[EPW];
            #pragma unroll
            for (int i = 0; i < EPW; i++) hk[i] = __shfl_sync(FULL, h[i], k);
            #pragma unroll
            for (int r = 0; r < 4; r++) {
                float w = We2s[k * 128 + r * 32 + lane];
                #pragma unroll
                for (int i = 0; i < EPW; i++) em[r][i] += hk[i] * w;
            }
        }
        #pragma unroll
        for (int r = 0; r < 4; r++)
            #pragma unroll
            for (int i = 0; i < EPW; i++) em[r][i] = fmaxf(em[r][i], 0.f);

        // ---- Layer 3: h2(64) = relu(pre2 + em(128) @ Wn1_m[128][64]) ----
        #pragma unroll
        for (int r2 = 0; r2 < 4; r2++) {
            #pragma unroll
            for (int kk = 0; kk < 32; kk++) {
                float v[EPW];
                #pragma unroll
                for (int i = 0; i < EPW; i++) v[i] = __shfl_sync(FULL, em[r2][i], kk);
                int krow = r2 * 32 + kk;
                float wa = Wn1s[krow * 64 + lane];
                float wb = Wn1s[krow * 64 + 32 + lane];
                #pragma unroll
                for (int i = 0; i < EPW; i++) {
                    p2a[i] += v[i] * wa;
                    p2b[i] += v[i] * wb;
                }
            }
        }
        #pragma unroll
        for (int i = 0; i < EPW; i++) {
            p2a[i] = fmaxf(p2a[i], 0.f);
            p2b[i] = fmaxf(p2b[i], 0.f);
        }

        // ---- Layer 4: nm(128) = relu(bn2 + h2(64) @ Wn2[64][128]) ----
        float nm[4][EPW];
        #pragma unroll
        for (int r = 0; r < 4; r++)
            #pragma unroll
            for (int i = 0; i < EPW; i++) nm[r][i] = bn2s[r * 32 + lane];
        #pragma unroll
        for (int r2 = 0; r2 < 2; r2++) {
            #pragma unroll
            for (int kk = 0; kk < 32; kk++) {
                float v[EPW];
                #pragma unroll
                for (int i = 0; i < EPW; i++)
                    v[i] = __shfl_sync(FULL, (r2 == 0) ? p2a[i] : p2b[i], kk);
                int krow = r2 * 32 + kk;
                #pragma unroll
                for (int r = 0; r < 4; r++) {
                    float w = Wn2s[krow * 128 + r * 32 + lane];
                    #pragma unroll
                    for (int i = 0; i < EPW; i++) nm[r][i] += v[i] * w;
                }
            }
        }

        // ---- scatter-add (relu then atomic) ----
        #pragma unroll
        for (int i = 0; i < EPW; i++) {
            if (!valid[i]) continue;
            #pragma unroll
            for (int r = 0; r < 4; r++) {
                float v = fmaxf(nm[r][i], 0.f);
                atomicAdd(&out[dst[i] * 128 + r * 32 + lane], v);
            }
        }
    }
}

// ---------------------------------------------------------------------------
extern "C" void kernel_launch(void* const* d_in, const int* in_sizes, int n_in,
                              void* d_out, int out_size) {
    const float* nf  = (const float*)d_in[0];
    const float* ef  = (const float*)d_in[1];
    const int*   ei  = (const int*)  d_in[2];
    const float* We1 = (const float*)d_in[3];
    const float* be1 = (const float*)d_in[4];
    const float* We2 = (const float*)d_in[5];
    const float* be2 = (const float*)d_in[6];
    const float* Wn1 = (const float*)d_in[7];
    const float* bn1 = (const float*)d_in[8];
    const float* Wn2 = (const float*)d_in[9];
    const float* bn2 = (const float*)d_in[10];
    float* out = (float*)d_out;

    const int Nn = in_sizes[0] / NODE_DIM;
    const int E  = in_sizes[2] / 2;

    precompute_kernel<<<(Nn + 7) / 8, 128>>>(nf, We1, be1, Wn1, bn1, out, Nn);

    const int smem_bytes = (64*32 + 32*128 + 128*64 + 64*128 + 256) * sizeof(float);
    cudaFuncSetAttribute(edge_kernel,
                         cudaFuncAttributeMaxDynamicSharedMemorySize, smem_bytes);
    edge_kernel<<<296, TPB, smem_bytes>>>(ef, ei, We1, We2, be2, Wn1, Wn2, bn2, out, E);
}

// round 2
// speedup vs baseline: 1.1158x; 1.1158x over previous
#include <cuda_runtime.h>

#define NODE_DIM 128
#define EDGE_DIM 64
#define MAXN 50000

typedef unsigned long long u64;

// Per-node precomputed projections (128 cols):
// [0:32)   nf@We1[0:128]   + be1   (src slice, bias folded)
// [32:64)  nf@We1[128:256]          (dst slice)
// [64:128) nf@Wn1[0:128]   + bn1   (node-MLP dst slice)
__device__ __align__(16) float g_P[MAXN * 128];

// ---------------- f32x2 packed-math helpers (sm_10x) ----------------
__device__ __forceinline__ u64 pk2(float lo, float hi) {
    u64 r;
    asm("mov.b64 %0, {%1, %2};" : "=l"(r)
        : "r"(__float_as_uint(lo)), "r"(__float_as_uint(hi)));
    return r;
}
__device__ __forceinline__ u64 pk1(float a) { return pk2(a, a); }
__device__ __forceinline__ float2 up2(u64 v) {
    unsigned lo, hi;
    asm("mov.b64 {%0, %1}, %2;" : "=r"(lo), "=r"(hi) : "l"(v));
    return make_float2(__uint_as_float(lo), __uint_as_float(hi));
}
__device__ __forceinline__ u64 fma2(u64 a, u64 b, u64 c) {
    u64 d;
    asm("fma.rn.f32x2 %0, %1, %2, %3;" : "=l"(d) : "l"(a), "l"(b), "l"(c));
    return d;
}
__device__ __forceinline__ void red4(float* p, float a, float b, float c, float d) {
    asm volatile("red.global.add.v4.f32 [%0], {%1, %2, %3, %4};"
                 :: "l"(p), "f"(a), "f"(b), "f"(c), "f"(d) : "memory");
}

// ---------------------------------------------------------------------------
// Precompute: 8 nodes/block, 128 threads (thread j = output col j).
// Also initializes out = node_features.
// ---------------------------------------------------------------------------
__global__ void __launch_bounds__(128) precompute_kernel(
    const float* __restrict__ nf,
    const float* __restrict__ We1,
    const float* __restrict__ be1,
    const float* __restrict__ Wn1,
    const float* __restrict__ bn1,
    float* __restrict__ out, int Nn)
{
    __shared__ float nfs[8][NODE_DIM];
    const int nb  = blockIdx.x * 8;
    const int tid = threadIdx.x;

    #pragma unroll
    for (int i = 0; i < 8; i++) {
        int n = nb + i;
        if (n < Nn) {
            float v = nf[n * NODE_DIM + tid];
            nfs[i][tid] = v;
            out[n * NODE_DIM + tid] = v;
        } else {
            nfs[i][tid] = 0.f;
        }
    }
    __syncthreads();

    const int j = tid;
    const float* wcol;
    int stride;
    float bias;
    if (j < 32)      { wcol = We1 + j;                 stride = 32; bias = be1[j]; }
    else if (j < 64) { wcol = We1 + 128 * 32 + (j-32); stride = 32; bias = 0.f; }
    else             { wcol = Wn1 + (j - 64);          stride = 64; bias = bn1[j-64]; }

    float acc[8];
    #pragma unroll
    for (int i = 0; i < 8; i++) acc[i] = bias;

    #pragma unroll 4
    for (int k = 0; k < NODE_DIM; k += 2) {
        float w0 = wcol[k * stride];
        float w1 = wcol[(k + 1) * stride];
        #pragma unroll
        for (int i = 0; i < 8; i++) {
            float2 v = *(const float2*)&nfs[i][k];
            acc[i] += v.x * w0;
            acc[i] += v.y * w1;
        }
    }

    #pragma unroll
    for (int i = 0; i < 8; i++) {
        int n = nb + i;
        if (n < Nn) g_P[n * 128 + tid] = acc[i];
    }
}

// ---------------------------------------------------------------------------
// Edge kernel: lane = edge. 32 edges per warp-tile, grid-stride.
// Activations live in registers; weights in smem read via broadcast LDS.128;
// all math in packed f32x2 (column pairs). No shuffles.
// ---------------------------------------------------------------------------
#define TPB 128

__global__ void __launch_bounds__(TPB, 2) edge_kernel(
    const float* __restrict__ ef,
    const int*   __restrict__ eidx,
    const float* __restrict__ We1,
    const float* __restrict__ We2,
    const float* __restrict__ be2,
    const float* __restrict__ Wn1,
    const float* __restrict__ Wn2,
    const float* __restrict__ bn2,
    float* __restrict__ out, int E)
{
    extern __shared__ float smem[];
    float* We1s = smem;                 // [64][32]   edge rows of We1
    float* We2s = We1s + 64 * 32;       // [32][128]
    float* Wn1s = We2s + 32 * 128;      // [128][64]  msg rows of Wn1
    float* Wn2s = Wn1s + 128 * 64;      // [64][128]
    float* be2s = Wn2s + 64 * 128;      // [128]
    float* bn2s = be2s + 128;           // [128]

    const int tid = threadIdx.x;
    for (int i = tid; i < 64 * 32;  i += TPB) We1s[i] = We1[256 * 32 + i];
    for (int i = tid; i < 32 * 128; i += TPB) We2s[i] = We2[i];
    for (int i = tid; i < 128 * 64; i += TPB) Wn1s[i] = Wn1[128 * 64 + i];
    for (int i = tid; i < 64 * 128; i += TPB) Wn2s[i] = Wn2[i];
    if (tid < 128) { be2s[tid] = be2[tid]; bn2s[tid] = bn2[tid]; }
    __syncthreads();

    const int lane  = tid & 31;
    const int gwarp = blockIdx.x * (TPB / 32) + (tid >> 5);
    const int nwarp = gridDim.x * (TPB / 32);

    for (int base = gwarp * 32; base < E; base += nwarp * 32) {
        const int e = base + lane;
        const bool valid = (e < E);
        const int ee = valid ? e : 0;
        const int s = eidx[ee];
        const int d = eidx[E + ee];
        const float4* Ps = (const float4*)(g_P + (size_t)s * 128);
        const float4* Pd = (const float4*)(g_P + (size_t)d * 128);

        // ---------------- Layer 1: h1(32) = relu(pre1 + ef(64) @ We1_e) ----
        u64 acc1[16];
        #pragma unroll
        for (int i = 0; i < 8; i++) {
            float4 a = Ps[i];       // src slice [0:32)
            float4 b = Pd[8 + i];   // dst slice [32:64)
            acc1[2*i]   = pk2(a.x + b.x, a.y + b.y);
            acc1[2*i+1] = pk2(a.z + b.z, a.w + b.w);
        }
        const float4* ef4 = (const float4*)(ef + (size_t)ee * EDGE_DIM);
        #pragma unroll
        for (int h = 0; h < 2; h++) {
            float4 A[8];
            #pragma unroll
            for (int i = 0; i < 8; i++) A[i] = ef4[h * 8 + i];
            #pragma unroll
            for (int q = 0; q < 8; q++) {
                float as[4] = {A[q].x, A[q].y, A[q].z, A[q].w};
                #pragma unroll
                for (int sub = 0; sub < 4; sub++) {
                    const int k = h * 32 + q * 4 + sub;
                    u64 a2 = pk1(as[sub]);
                    const ulonglong2* w = (const ulonglong2*)(We1s + k * 32);
                    #pragma unroll
                    for (int j = 0; j < 8; j++) {
                        ulonglong2 ww = w[j];
                        acc1[2*j]   = fma2(a2, ww.x, acc1[2*j]);
                        acc1[2*j+1] = fma2(a2, ww.y, acc1[2*j+1]);
                    }
                }
            }
        }
        float h1v[32];
        #pragma unroll
        for (int i = 0; i < 16; i++) {
            float2 f = up2(acc1[i]);
            h1v[2*i]   = fmaxf(f.x, 0.f);
            h1v[2*i+1] = fmaxf(f.y, 0.f);
        }

        // ------------- Layers 2+3 fused (em in chunks of 8 cols) ----------
        // h2acc(64) starts at pre2 = P[d][64:128)
        u64 hacc[32];
        #pragma unroll
        for (int i = 0; i < 16; i++) {
            float4 p = Pd[16 + i];
            hacc[2*i]   = pk2(p.x, p.y);
            hacc[2*i+1] = pk2(p.z, p.w);
        }
        #pragma unroll
        for (int c = 0; c < 16; c++) {
            u64 em[4];
            {
                const ulonglong2* bb = (const ulonglong2*)(be2s + c * 8);
                ulonglong2 b0 = bb[0], b1 = bb[1];
                em[0] = b0.x; em[1] = b0.y; em[2] = b1.x; em[3] = b1.y;
            }
            #pragma unroll
            for (int k = 0; k < 32; k++) {
                u64 a2 = pk1(h1v[k]);
                const ulonglong2* w = (const ulonglong2*)(We2s + k * 128 + c * 8);
                ulonglong2 w0 = w[0], w1 = w[1];
                em[0] = fma2(a2, w0.x, em[0]);
                em[1] = fma2(a2, w0.y, em[1]);
                em[2] = fma2(a2, w1.x, em[2]);
                em[3] = fma2(a2, w1.y, em[3]);
            }
            float emv[8];
            #pragma unroll
            for (int i = 0; i < 4; i++) {
                float2 f = up2(em[i]);
                emv[2*i]   = fmaxf(f.x, 0.f);
                emv[2*i+1] = fmaxf(f.y, 0.f);
            }
            #pragma unroll
            for (int kk = 0; kk < 8; kk++) {
                u64 a2 = pk1(emv[kk]);
                const ulonglong2* w = (const ulonglong2*)(Wn1s + (c * 8 + kk) * 64);
                #pragma unroll
                for (int j = 0; j < 16; j++) {
                    ulonglong2 ww = w[j];
                    hacc[2*j]   = fma2(a2, ww.x, hacc[2*j]);
                    hacc[2*j+1] = fma2(a2, ww.y, hacc[2*j+1]);
                }
            }
        }

        // ---------------- Layer 4: nm(128) in chunks of 32 + scatter ------
        float h2v[64];
        #pragma unroll
        for (int i = 0; i < 32; i++) {
            float2 f = up2(hacc[i]);
            h2v[2*i]   = fmaxf(f.x, 0.f);
            h2v[2*i+1] = fmaxf(f.y, 0.f);
        }
        float* outp = out + (size_t)d * 128;
        #pragma unroll
        for (int c = 0; c < 4; c++) {
            u64 nm[16];
            {
                const ulonglong2* bb = (const ulonglong2*)(bn2s + c * 32);
                #pragma unroll
                for (int i = 0; i < 8; i++) {
                    ulonglong2 b = bb[i];
                    nm[2*i] = b.x; nm[2*i+1] = b.y;
                }
            }
            #pragma unroll
            for (int k = 0; k < 64; k++) {
                u64 a2 = pk1(h2v[k]);
                const ulonglong2* w = (const ulonglong2*)(Wn2s + k * 128 + c * 32);
                #pragma unroll
                for (int j = 0; j < 8; j++) {
                    ulonglong2 ww = w[j];
                    nm[2*j]   = fma2(a2, ww.x, nm[2*j]);
                    nm[2*j+1] = fma2(a2, ww.y, nm[2*j+1]);
                }
            }
            if (valid) {
                #pragma unroll
                for (int g = 0; g < 4; g++) {
                    float2 f0 = up2(nm[4*g]);
                    float2 f1 = up2(nm[4*g + 1]);
                    float2 f2 = up2(nm[4*g + 2]);
                    float2 f3 = up2(nm[4*g + 3]);
                    red4(outp + c * 32 + g * 8,
                         fmaxf(f0.x, 0.f), fmaxf(f0.y, 0.f),
                         fmaxf(f1.x, 0.f), fmaxf(f1.y, 0.f));
                    red4(outp + c * 32 + g * 8 + 4,
                         fmaxf(f2.x, 0.f), fmaxf(f2.y, 0.f),
                         fmaxf(f3.x, 0.f), fmaxf(f3.y, 0.f));
                }
            }
        }
    }
}

// ---------------------------------------------------------------------------
extern "C" void kernel_launch(void* const* d_in, const int* in_sizes, int n_in,
                              void* d_out, int out_size) {
    const float* nf  = (const float*)d_in[0];
    const float* ef  = (const float*)d_in[1];
    const int*   ei  = (const int*)  d_in[2];
    const float* We1 = (const float*)d_in[3];
    const float* be1 = (const float*)d_in[4];
    const float* We2 = (const float*)d_in[5];
    const float* be2 = (const float*)d_in[6];
    const float* Wn1 = (const float*)d_in[7];
    const float* bn1 = (const float*)d_in[8];
    const float* Wn2 = (const float*)d_in[9];
    const float* bn2 = (const float*)d_in[10];
    float* out = (float*)d_out;

    const int Nn = in_sizes[0] / NODE_DIM;
    const int E  = in_sizes[2] / 2;

    precompute_kernel<<<(Nn + 7) / 8, 128>>>(nf, We1, be1, Wn1, bn1, out, Nn);

    const int smem_bytes = (64*32 + 32*128 + 128*64 + 64*128 + 256) * sizeof(float);
    cudaFuncSetAttribute(edge_kernel,
                         cudaFuncAttributeMaxDynamicSharedMemorySize, smem_bytes);
    edge_kernel<<<296, TPB, smem_bytes>>>(ef, ei, We1, We2, be2, Wn1, Wn2, bn2, out, E);
}

// round 4
// speedup vs baseline: 2.9332x; 2.6288x over previous
#include <cuda_runtime.h>
#include <cstdint>

#define TPB 256
#define NWARP 8
#define TILE_E (NWARP * 32)
#define MAXN 50000

__device__ __align__(16) float g_P[MAXN * 128];

// ------------------------------- helpers ----------------------------------
__device__ __forceinline__ uint32_t f2tf(float f) {   // RNA round to tf32
    uint32_t r; asm("cvt.rna.tf32.f32 %0, %1;" : "=r"(r) : "f"(f)); return r;
}
__device__ __forceinline__ void red4(float* p, float a, float b, float c, float d) {
    asm volatile("red.global.add.v4.f32 [%0], {%1,%2,%3,%4};"
                 :: "l"(p), "f"(a), "f"(b), "f"(c), "f"(d) : "memory");
}
// D(16x8,f32) += A(16x8,tf32) @ B(8x8,tf32)
__device__ __forceinline__ void mma8(float* c, uint32_t a0, uint32_t a1,
                                     uint32_t a2, uint32_t a3,
                                     uint32_t b0, uint32_t b1) {
    asm volatile("mma.sync.aligned.m16n8k8.row.col.f32.tf32.tf32.f32 "
                 "{%0,%1,%2,%3}, {%4,%5,%6,%7}, {%8,%9}, {%0,%1,%2,%3};"
                 : "+f"(c[0]), "+f"(c[1]), "+f"(c[2]), "+f"(c[3])
                 : "r"(a0), "r"(a1), "r"(a2), "r"(a3), "r"(b0), "r"(b1));
}

// ---------------------------------------------------------------------------
// Precompute: per-node projections; also initializes out = node_features.
// P[n][0:32)=nf@We1[0:128]+be1, [32:64)=nf@We1[128:256], [64:128)=nf@Wn1[0:128]+bn1
// ---------------------------------------------------------------------------
__global__ void __launch_bounds__(128) precompute_kernel(
    const float* __restrict__ nf,
    const float* __restrict__ We1,
    const float* __restrict__ be1,
    const float* __restrict__ Wn1,
    const float* __restrict__ bn1,
    float* __restrict__ out, int Nn)
{
    __shared__ float nfs[8][128];
    const int nb  = blockIdx.x * 8;
    const int tid = threadIdx.x;

    #pragma unroll
    for (int i = 0; i < 8; i++) {
        int n = nb + i;
        if (n < Nn) {
            float v = nf[n * 128 + tid];
            nfs[i][tid] = v;
            out[n * 128 + tid] = v;
        } else nfs[i][tid] = 0.f;
    }
    __syncthreads();

    const int j = tid;
    const float* wcol; int stride; float bias;
    if (j < 32)      { wcol = We1 + j;                 stride = 32; bias = be1[j]; }
    else if (j < 64) { wcol = We1 + 128 * 32 + (j-32); stride = 32; bias = 0.f; }
    else             { wcol = Wn1 + (j - 64);          stride = 64; bias = bn1[j-64]; }

    float acc[8];
    #pragma unroll
    for (int i = 0; i < 8; i++) acc[i] = bias;

    #pragma unroll 4
    for (int k = 0; k < 128; k += 2) {
        float w0 = wcol[k * stride];
        float w1 = wcol[(k + 1) * stride];
        #pragma unroll
        for (int i = 0; i < 8; i++) {
            float2 v = *(const float2*)&nfs[i][k];
            acc[i] += v.x * w0;
            acc[i] += v.y * w1;
        }
    }
    #pragma unroll
    for (int i = 0; i < 8; i++) {
        int n = nb + i;
        if (n < Nn) g_P[n * 128 + tid] = acc[i];
    }
}

// ---------------------------------------------------------------------------
// Edge kernel: persistent, 8 independent warps x 32 edges, mma.sync tf32.
// smem: weights transposed [N][K] (padded pitches, tf32 bits) + per-warp scratch.
// ---------------------------------------------------------------------------
#define OFF_W1  0            // [32][68]  -> 8704
#define OFF_W2  8704         // [128][36] -> 18432
#define OFF_W3  27136        // [64][132] -> 33792
#define OFF_W4  60928        // [128][68] -> 34816
#define OFF_BE2 95744
#define OFF_BN2 96256
#define OFF_SCR 96768
#define WS_BYTES 13824       // h1[32][36] | em[32][36] | nm[32][36]; h2[32][68] overlaps h1+em
#define SM_TOTAL (OFF_SCR + NWARP * WS_BYTES)   // 207360

__global__ void __launch_bounds__(TPB, 1) edge_mma_kernel(
    const float* __restrict__ ef,
    const int*   __restrict__ eidx,
    const float* __restrict__ We1,
    const float* __restrict__ We2,
    const float* __restrict__ be2,
    const float* __restrict__ Wn1,
    const float* __restrict__ Wn2,
    const float* __restrict__ bn2,
    float* __restrict__ out, int E, int ntiles)
{
    extern __shared__ char sm[];
    uint32_t* W1s = (uint32_t*)(sm + OFF_W1);
    uint32_t* W2s = (uint32_t*)(sm + OFF_W2);
    uint32_t* W3s = (uint32_t*)(sm + OFF_W3);
    uint32_t* W4s = (uint32_t*)(sm + OFF_W4);
    float* be2s = (float*)(sm + OFF_BE2);
    float* bn2s = (float*)(sm + OFF_BN2);

    const int tid = threadIdx.x;
    for (int i = tid; i < 32 * 64;  i += TPB) { int n = i >> 6, k = i & 63;  W1s[n*68  + k] = f2tf(We1[(256 + k) * 32 + n]); }
    for (int i = tid; i < 128 * 32; i += TPB) { int n = i >> 5, k = i & 31;  W2s[n*36  + k] = f2tf(We2[k * 128 + n]); }
    for (int i = tid; i < 64 * 128; i += TPB) { int n = i >> 7, k = i & 127; W3s[n*132 + k] = f2tf(Wn1[(128 + k) * 64 + n]); }
    for (int i = tid; i < 128 * 64; i += TPB) { int n = i >> 6, k = i & 63;  W4s[n*68  + k] = f2tf(Wn2[k * 128 + n]); }
    if (tid < 128) { be2s[tid] = be2[tid]; bn2s[tid] = bn2[tid]; }
    __syncthreads();

    const int lane = tid & 31, wid = tid >> 5;
    const int g = lane >> 2, q = lane & 3;
    char* ws = sm + OFF_SCR + wid * WS_BYTES;
    uint32_t* h1s = (uint32_t*)ws;            // pitch 36
    uint32_t* ems = (uint32_t*)(ws + 4608);   // pitch 36
    uint32_t* h2s = (uint32_t*)ws;            // pitch 68 (overlaps h1+em; h1/em dead by then)
    float*    nms = (float*)(ws + 9216);      // pitch 36

    for (int t = blockIdx.x; t < ntiles; t += gridDim.x) {
        const int eb = t * TILE_E + wid * 32;

        // row bookkeeping: m = 2*mt + h -> warp-local rows {g, g+8, g+16, g+24}
        int er[4], sidx[4], didx[4];
        #pragma unroll
        for (int m = 0; m < 4; m++) {
            int r = eb + g + ((m >> 1) << 4) + ((m & 1) << 3);
            er[m]   = (r < E) ? r : (E - 1);
            sidx[m] = eidx[er[m]];
            didx[m] = eidx[E + er[m]];
        }

        // ================= L1: h1(32x32) = relu(pre1 + ef @ W1e) ==========
        float c1[2][4][4];
        #pragma unroll
        for (int mt = 0; mt < 2; mt++)
            #pragma unroll
            for (int nt = 0; nt < 4; nt++) {
                const int col = 8 * nt + 2 * q;
                #pragma unroll
                for (int h = 0; h < 2; h++) {
                    float2 ps = *(const float2*)&g_P[(size_t)sidx[2*mt+h] * 128 + col];
                    float2 pd = *(const float2*)&g_P[(size_t)didx[2*mt+h] * 128 + 32 + col];
                    c1[mt][nt][2*h]   = ps.x + pd.x;
                    c1[mt][nt][2*h+1] = ps.y + pd.y;
                }
            }
        #pragma unroll
        for (int kt = 0; kt < 8; kt++) {
            uint32_t a[2][4];
            #pragma unroll
            for (int mt = 0; mt < 2; mt++) {
                a[mt][0] = f2tf(ef[(size_t)er[2*mt]   * 64 + 8*kt + q]);
                a[mt][1] = f2tf(ef[(size_t)er[2*mt+1] * 64 + 8*kt + q]);
                a[mt][2] = f2tf(ef[(size_t)er[2*mt]   * 64 + 8*kt + q + 4]);
                a[mt][3] = f2tf(ef[(size_t)er[2*mt+1] * 64 + 8*kt + q + 4]);
            }
            #pragma unroll
            for (int nt = 0; nt < 4; nt++) {
                uint32_t b0 = W1s[(8*nt+g)*68 + 8*kt + q];
                uint32_t b1 = W1s[(8*nt+g)*68 + 8*kt + q + 4];
                mma8(c1[0][nt], a[0][0],a[0][1],a[0][2],a[0][3], b0, b1);
                mma8(c1[1][nt], a[1][0],a[1][1],a[1][2],a[1][3], b0, b1);
            }
        }
        #pragma unroll
        for (int mt = 0; mt < 2; mt++)
            #pragma unroll
            for (int nt = 0; nt < 4; nt++) {
                const int col = 8 * nt + 2 * q;
                uint2 v0 = { f2tf(fmaxf(c1[mt][nt][0], 0.f)), f2tf(fmaxf(c1[mt][nt][1], 0.f)) };
                uint2 v1 = { f2tf(fmaxf(c1[mt][nt][2], 0.f)), f2tf(fmaxf(c1[mt][nt][3], 0.f)) };
                *(uint2*)&h1s[(g + 16*mt) * 36 + col]     = v0;
                *(uint2*)&h1s[(g + 8 + 16*mt) * 36 + col] = v1;
            }
        __syncwarp();

        // ========== L2+L3 fused: h2(32x64) = relu(pre2 + em @ Wn1m) =======
        float c3[2][8][4];
        #pragma unroll
        for (int mt = 0; mt < 2; mt++)
            #pragma unroll
            for (int nt = 0; nt < 8; nt++) {
                const int col = 8 * nt + 2 * q;
                #pragma unroll
                for (int h = 0; h < 2; h++) {
                    float2 pd = *(const float2*)&g_P[(size_t)didx[2*mt+h] * 128 + 64 + col];
                    c3[mt][nt][2*h]   = pd.x;
                    c3[mt][nt][2*h+1] = pd.y;
                }
            }
        #pragma unroll
        for (int ch = 0; ch < 4; ch++) {
            // --- L2 chunk: em_c(32x32) = relu(be2_c + h1 @ We2_c) ---
            float c2[2][4][4];
            #pragma unroll
            for (int nt = 0; nt < 4; nt++) {
                float2 b = *(const float2*)&be2s[32*ch + 8*nt + 2*q];
                #pragma unroll
                for (int mt = 0; mt < 2; mt++) {
                    c2[mt][nt][0] = b.x; c2[mt][nt][1] = b.y;
                    c2[mt][nt][2] = b.x; c2[mt][nt][3] = b.y;
                }
            }
            #pragma unroll
            for (int kt = 0; kt < 4; kt++) {
                uint32_t a[2][4];
                #pragma unroll
                for (int mt = 0; mt < 2; mt++) {
                    int r0 = (g + 16*mt) * 36, r1 = (g + 8 + 16*mt) * 36;
                    a[mt][0] = h1s[r0 + 8*kt + q];
                    a[mt][1] = h1s[r1 + 8*kt + q];
                    a[mt][2] = h1s[r0 + 8*kt + q + 4];
                    a[mt][3] = h1s[r1 + 8*kt + q + 4];
                }
                #pragma unroll
                for (int nt = 0; nt < 4; nt++) {
                    uint32_t b0 = W2s[(32*ch + 8*nt + g)*36 + 8*kt + q];
                    uint32_t b1 = W2s[(32*ch + 8*nt + g)*36 + 8*kt + q + 4];
                    mma8(c2[0][nt], a[0][0],a[0][1],a[0][2],a[0][3], b0, b1);
                    mma8(c2[1][nt], a[1][0],a[1][1],a[1][2],a[1][3], b0, b1);
                }
            }
            #pragma unroll
            for (int mt = 0; mt < 2; mt++)
                #pragma unroll
                for (int nt = 0; nt < 4; nt++) {
                    const int col = 8 * nt + 2 * q;
                    uint2 v0 = { f2tf(fmaxf(c2[mt][nt][0], 0.f)), f2tf(fmaxf(c2[mt][nt][1], 0.f)) };
                    uint2 v1 = { f2tf(fmaxf(c2[mt][nt][2], 0.f)), f2tf(fmaxf(c2[mt][nt][3], 0.f)) };
                    *(uint2*)&ems[(g + 16*mt) * 36 + col]     = v0;
                    *(uint2*)&ems[(g + 8 + 16*mt) * 36 + col] = v1;
                }
            __syncwarp();
            // --- L3 accumulate over this K-chunk ---
            #pragma unroll
            for (int kt = 0; kt < 4; kt++) {
                uint32_t a[2][4];
                #pragma unroll
                for (int mt = 0; mt < 2; mt++) {
                    int r0 = (g + 16*mt) * 36, r1 = (g + 8 + 16*mt) * 36;
                    a[mt][0] = ems[r0 + 8*kt + q];
                    a[mt][1] = ems[r1 + 8*kt + q];
                    a[mt][2] = ems[r0 + 8*kt + q + 4];
                    a[mt][3] = ems[r1 + 8*kt + q + 4];
                }
                #pragma unroll
                for (int nt = 0; nt < 8; nt++) {
                    uint32_t b0 = W3s[(8*nt+g)*132 + 32*ch + 8*kt + q];
                    uint32_t b1 = W3s[(8*nt+g)*132 + 32*ch + 8*kt + q + 4];
                    mma8(c3[0][nt], a[0][0],a[0][1],a[0][2],a[0][3], b0, b1);
                    mma8(c3[1][nt], a[1][0],a[1][1],a[1][2],a[1][3], b0, b1);
                }
            }
            __syncwarp();   // before next chunk overwrites ems
        }
        // h2 -> smem (pitch 68; overlaps dead h1/em)
        #pragma unroll
        for (int mt = 0; mt < 2; mt++)
            #pragma unroll
            for (int nt = 0; nt < 8; nt++) {
                const int col = 8 * nt + 2 * q;
                uint2 v0 = { f2tf(fmaxf(c3[mt][nt][0], 0.f)), f2tf(fmaxf(c3[mt][nt][1], 0.f)) };
                uint2 v1 = { f2tf(fmaxf(c3[mt][nt][2], 0.f)), f2tf(fmaxf(c3[mt][nt][3], 0.f)) };
                *(uint2*)&h2s[(g + 16*mt) * 68 + col]     = v0;
                *(uint2*)&h2s[(g + 8 + 16*mt) * 68 + col] = v1;
            }
        __syncwarp();

        // ============ L4: nm(32x128) = relu(bn2 + h2 @ Wn2), scatter ======
        const int rl = eb + lane;
        const bool vl = (rl < E);
        const int dl = eidx[E + (vl ? rl : 0)];
        #pragma unroll
        for (int n4 = 0; n4 < 4; n4++) {
            float c4[2][4][4];
            #pragma unroll
            for (int nt = 0; nt < 4; nt++) {
                float2 b = *(const float2*)&bn2s[32*n4 + 8*nt + 2*q];
                #pragma unroll
                for (int mt = 0; mt < 2; mt++) {
                    c4[mt][nt][0] = b.x; c4[mt][nt][1] = b.y;
                    c4[mt][nt][2] = b.x; c4[mt][nt][3] = b.y;
                }
            }
            #pragma unroll
            for (int kt = 0; kt < 8; kt++) {
                uint32_t a[2][4];
                #pragma unroll
                for (int mt = 0; mt < 2; mt++) {
                    int r0 = (g + 16*mt) * 68, r1 = (g + 8 + 16*mt) * 68;
                    a[mt][0] = h2s[r0 + 8*kt + q];
                    a[mt][1] = h2s[r1 + 8*kt + q];
                    a[mt][2] = h2s[r0 + 8*kt + q + 4];
                    a[mt][3] = h2s[r1 + 8*kt + q + 4];
                }
                #pragma unroll
                for (int nt = 0; nt < 4; nt++) {
                    uint32_t b0 = W4s[(32*n4 + 8*nt + g)*68 + 8*kt + q];
                    uint32_t b1 = W4s[(32*n4 + 8*nt + g)*68 + 8*kt + q + 4];
                    mma8(c4[0][nt], a[0][0],a[0][1],a[0][2],a[0][3], b0, b1);
                    mma8(c4[1][nt], a[1][0],a[1][1],a[1][2],a[1][3], b0, b1);
                }
            }
            __syncwarp();   // previous n4's nms reads done
            #pragma unroll
            for (int mt = 0; mt < 2; mt++)
                #pragma unroll
                for (int nt = 0; nt < 4; nt++) {
                    const int col = 8 * nt + 2 * q;
                    float2 v0 = { fmaxf(c4[mt][nt][0], 0.f), fmaxf(c4[mt][nt][1], 0.f) };
                    float2 v1 = { fmaxf(c4[mt][nt][2], 0.f), fmaxf(c4[mt][nt][3], 0.f) };
                    *(float2*)&nms[(g + 16*mt) * 36 + col]     = v0;
                    *(float2*)&nms[(g + 8 + 16*mt) * 36 + col] = v1;
                }
            __syncwarp();
            if (vl) {
                float* outp = out + (size_t)dl * 128 + 32 * n4;
                #pragma unroll
                for (int j = 0; j < 8; j++) {
                    float4 v = *(const float4*)&nms[lane * 36 + 4 * j];
                    red4(outp + 4 * j, v.x, v.y, v.z, v.w);
                }
            }
        }
    }
}

// ---------------------------------------------------------------------------
extern "C" void kernel_launch(void* const* d_in, const int* in_sizes, int n_in,
                              void* d_out, int out_size) {
    const float* nf  = (const float*)d_in[0];
    const float* ef  = (const float*)d_in[1];
    const int*   ei  = (const int*)  d_in[2];
    const float* We1 = (const float*)d_in[3];
    const float* be1 = (const float*)d_in[4];
    const float* We2 = (const float*)d_in[5];
    const float* be2 = (const float*)d_in[6];
    const float* Wn1 = (const float*)d_in[7];
    const float* bn1 = (const float*)d_in[8];
    const float* Wn2 = (const float*)d_in[9];
    const float* bn2 = (const float*)d_in[10];
    float* out = (float*)d_out;

    const int Nn = in_sizes[0] / 128;
    const int E  = in_sizes[2] / 2;
    const int ntiles = (E + TILE_E - 1) / TILE_E;

    precompute_kernel<<<(Nn + 7) / 8, 128>>>(nf, We1, be1, Wn1, bn1, out, Nn);

    cudaFuncSetAttribute(edge_mma_kernel,
                         cudaFuncAttributeMaxDynamicSharedMemorySize, SM_TOTAL);
    edge_mma_kernel<<<152, TPB, SM_TOTAL>>>(ef, ei, We1, We2, be2,
                                            Wn1, Wn2, bn2, out, E, ntiles);
}

// round 5
// speedup vs baseline: 3.7423x; 1.2758x over previous
#include <cuda_runtime.h>
#include <cstdint>

#define TPB 384
#define NWARP 12
#define TILE_E (NWARP * 32)
#define MAXN 50000

__device__ __align__(16) float g_P[MAXN * 128];

// ------------------------------- helpers ----------------------------------
__device__ __forceinline__ uint32_t f2tf(float f) {   // RNA round to tf32
    uint32_t r; asm("cvt.rna.tf32.f32 %0, %1;" : "=r"(r) : "f"(f)); return r;
}
__device__ __forceinline__ void red2(float* p, float a, float b) {
    asm volatile("red.global.add.v2.f32 [%0], {%1,%2};"
                 :: "l"(p), "f"(a), "f"(b) : "memory");
}
// D(16x8,f32) += A(16x8,tf32) @ B(8x8,tf32)
__device__ __forceinline__ void mma8(float* c, uint32_t a0, uint32_t a1,
                                     uint32_t a2, uint32_t a3,
                                     uint32_t b0, uint32_t b1) {
    asm volatile("mma.sync.aligned.m16n8k8.row.col.f32.tf32.tf32.f32 "
                 "{%0,%1,%2,%3}, {%4,%5,%6,%7}, {%8,%9}, {%0,%1,%2,%3};"
                 : "+f"(c[0]), "+f"(c[1]), "+f"(c[2]), "+f"(c[3])
                 : "r"(a0), "r"(a1), "r"(a2), "r"(a3), "r"(b0), "r"(b1));
}
// Convert C-fragment (16x8 tile) to A-fragment of the same tile (relu + tf32),
// pure register shuffles: dest (g,q) <- src lane g*4+(q>>1), slot q&1.
__device__ __forceinline__ void frag_c2a(float c0, float c1, float c2, float c3,
                                         int lane, uint32_t a[4]) {
    const unsigned F = 0xFFFFFFFFu;
    uint32_t r0 = f2tf(fmaxf(c0, 0.f)), r1 = f2tf(fmaxf(c1, 0.f));
    uint32_t r2 = f2tf(fmaxf(c2, 0.f)), r3 = f2tf(fmaxf(c3, 0.f));
    int l1 = (lane & 28) | ((lane & 3) >> 1);
    int l2 = l1 + 2;
    bool odd = lane & 1;
    uint32_t s0 = __shfl_sync(F, r0, l1), s1 = __shfl_sync(F, r1, l1);
    uint32_t s2 = __shfl_sync(F, r2, l1), s3 = __shfl_sync(F, r3, l1);
    uint32_t t0 = __shfl_sync(F, r0, l2), t1 = __shfl_sync(F, r1, l2);
    uint32_t t2 = __shfl_sync(F, r2, l2), t3 = __shfl_sync(F, r3, l2);
    a[0] = odd ? s1 : s0;  a[1] = odd ? s3 : s2;
    a[2] = odd ? t1 : t0;  a[3] = odd ? t3 : t2;
}

// ---------------------------------------------------------------------------
// Precompute: 16 nodes/block; also initializes out = node_features.
// P[n][0:32)=nf@We1[0:128]+be1, [32:64)=nf@We1[128:256], [64:128)=nf@Wn1[0:128]+bn1
// ---------------------------------------------------------------------------
__global__ void __launch_bounds__(128) precompute_kernel(
    const float* __restrict__ nf,
    const float* __restrict__ We1,
    const float* __restrict__ be1,
    const float* __restrict__ Wn1,
    const float* __restrict__ bn1,
    float* __restrict__ out, int Nn)
{
    __shared__ float nfs[16][128];
    const int nb  = blockIdx.x * 16;
    const int tid = threadIdx.x;

    #pragma unroll
    for (int i = 0; i < 16; i++) {
        int n = nb + i;
        if (n < Nn) {
            float v = nf[n * 128 + tid];
            nfs[i][tid] = v;
            out[n * 128 + tid] = v;
        } else nfs[i][tid] = 0.f;
    }
    __syncthreads();

    const int j = tid;
    const float* wcol; int stride; float bias;
    if (j < 32)      { wcol = We1 + j;                 stride = 32; bias = be1[j]; }
    else if (j < 64) { wcol = We1 + 128 * 32 + (j-32); stride = 32; bias = 0.f; }
    else             { wcol = Wn1 + (j - 64);          stride = 64; bias = bn1[j-64]; }

    float acc[16];
    #pragma unroll
    for (int i = 0; i < 16; i++) acc[i] = bias;

    #pragma unroll 2
    for (int k = 0; k < 128; k += 2) {
        float w0 = wcol[k * stride];
        float w1 = wcol[(k + 1) * stride];
        #pragma unroll
        for (int i = 0; i < 16; i++) {
            float2 v = *(const float2*)&nfs[i][k];
            acc[i] += v.x * w0;
            acc[i] += v.y * w1;
        }
    }
    #pragma unroll
    for (int i = 0; i < 16; i++) {
        int n = nb + i;
        if (n < Nn) g_P[n * 128 + tid] = acc[i];
    }
}

// ---------------------------------------------------------------------------
// Edge kernel: persistent, 12 independent warps x 32 edges, mma.sync tf32.
// Activations live in registers (shuffle-based fragment conversion); only h1
// takes a small per-warp smem roundtrip (reused by 4 K-chunks of layer 2).
// ---------------------------------------------------------------------------
#define OFF_W1  0            // [32][68]  -> 8704
#define OFF_W2  8704         // [128][36] -> 18432
#define OFF_W3  27136        // [64][132] -> 33792
#define OFF_W4  60928        // [128][68] -> 34816
#define OFF_BE2 95744
#define OFF_BN2 96256
#define OFF_SCR 96768
#define WS_BYTES 4608        // h1[32][36]
#define SM_TOTAL (OFF_SCR + NWARP * WS_BYTES)   // 152064

__global__ void __launch_bounds__(TPB, 1) edge_mma_kernel(
    const float* __restrict__ ef,
    const int*   __restrict__ eidx,
    const float* __restrict__ We1,
    const float* __restrict__ We2,
    const float* __restrict__ be2,
    const float* __restrict__ Wn1,
    const float* __restrict__ Wn2,
    const float* __restrict__ bn2,
    float* __restrict__ out, int E, int ntiles)
{
    extern __shared__ char sm[];
    uint32_t* W1s = (uint32_t*)(sm + OFF_W1);
    uint32_t* W2s = (uint32_t*)(sm + OFF_W2);
    uint32_t* W3s = (uint32_t*)(sm + OFF_W3);
    uint32_t* W4s = (uint32_t*)(sm + OFF_W4);
    float* be2s = (float*)(sm + OFF_BE2);
    float* bn2s = (float*)(sm + OFF_BN2);

    const int tid = threadIdx.x;
    for (int i = tid; i < 32 * 64;  i += TPB) { int n = i >> 6, k = i & 63;  W1s[n*68  + k] = f2tf(We1[(256 + k) * 32 + n]); }
    for (int i = tid; i < 128 * 32; i += TPB) { int n = i >> 5, k = i & 31;  W2s[n*36  + k] = f2tf(We2[k * 128 + n]); }
    for (int i = tid; i < 64 * 128; i += TPB) { int n = i >> 7, k = i & 127; W3s[n*132 + k] = f2tf(Wn1[(128 + k) * 64 + n]); }
    for (int i = tid; i < 128 * 64; i += TPB) { int n = i >> 6, k = i & 63;  W4s[n*68  + k] = f2tf(Wn2[k * 128 + n]); }
    if (tid < 128) { be2s[tid] = be2[tid]; bn2s[tid] = bn2[tid]; }
    __syncthreads();

    const int lane = tid & 31, wid = tid >> 5;
    const int g = lane >> 2, q = lane & 3;
    uint32_t* h1s = (uint32_t*)(sm + OFF_SCR + wid * WS_BYTES);   // pitch 36

    for (int t = blockIdx.x; t < ntiles; t += gridDim.x) {
        const int eb = t * TILE_E + wid * 32;

        // rows m = 2*mt + h  ->  warp-local rows {g, g+8, g+16, g+24}
        int er[4], sidx[4], didx[4];
        bool val[4];
        #pragma unroll
        for (int m = 0; m < 4; m++) {
            int r = eb + g + ((m >> 1) << 4) + ((m & 1) << 3);
            val[m] = (r < E);
            er[m]  = val[m] ? r : (E - 1);
            sidx[m] = eidx[er[m]];
            didx[m] = eidx[E + er[m]];
        }

        // ================= L1: h1(32x32) = relu(pre1 + ef @ W1e) ==========
        float c1[2][4][4];
        #pragma unroll
        for (int mt = 0; mt < 2; mt++)
            #pragma unroll
            for (int nt = 0; nt < 4; nt++) {
                const int col = 8 * nt + 2 * q;
                #pragma unroll
                for (int h = 0; h < 2; h++) {
                    float2 ps = *(const float2*)&g_P[(size_t)sidx[2*mt+h] * 128 + col];
                    float2 pd = *(const float2*)&g_P[(size_t)didx[2*mt+h] * 128 + 32 + col];
                    c1[mt][nt][2*h]   = ps.x + pd.x;
                    c1[mt][nt][2*h+1] = ps.y + pd.y;
                }
            }
        #pragma unroll
        for (int kt = 0; kt < 8; kt++) {
            uint32_t a[2][4];
            #pragma unroll
            for (int mt = 0; mt < 2; mt++) {
                a[mt][0] = f2tf(__ldg(&ef[(size_t)er[2*mt]   * 64 + 8*kt + q]));
                a[mt][1] = f2tf(__ldg(&ef[(size_t)er[2*mt+1] * 64 + 8*kt + q]));
                a[mt][2] = f2tf(__ldg(&ef[(size_t)er[2*mt]   * 64 + 8*kt + q + 4]));
                a[mt][3] = f2tf(__ldg(&ef[(size_t)er[2*mt+1] * 64 + 8*kt + q + 4]));
            }
            #pragma unroll
            for (int nt = 0; nt < 4; nt++) {
                uint32_t b0 = W1s[(8*nt+g)*68 + 8*kt + q];
                uint32_t b1 = W1s[(8*nt+g)*68 + 8*kt + q + 4];
                mma8(c1[0][nt], a[0][0],a[0][1],a[0][2],a[0][3], b0, b1);
                mma8(c1[1][nt], a[1][0],a[1][1],a[1][2],a[1][3], b0, b1);
            }
        }
        __syncwarp();      // previous tile's h1 reads done before overwrite
        #pragma unroll
        for (int mt = 0; mt < 2; mt++)
            #pragma unroll
            for (int nt = 0; nt < 4; nt++) {
                const int col = 8 * nt + 2 * q;
                uint2 v0 = { f2tf(fmaxf(c1[mt][nt][0], 0.f)), f2tf(fmaxf(c1[mt][nt][1], 0.f)) };
                uint2 v1 = { f2tf(fmaxf(c1[mt][nt][2], 0.f)), f2tf(fmaxf(c1[mt][nt][3], 0.f)) };
                *(uint2*)&h1s[(g + 16*mt) * 36 + col]     = v0;
                *(uint2*)&h1s[(g + 8 + 16*mt) * 36 + col] = v1;
            }
        __syncwarp();

        // ========== L2+L3 fused: h2(32x64) = relu(pre2 + em @ Wn1m) =======
        float c3[2][8][4];
        #pragma unroll
        for (int mt = 0; mt < 2; mt++)
            #pragma unroll
            for (int nt = 0; nt < 8; nt++) {
                const int col = 8 * nt + 2 * q;
                #pragma unroll
                for (int h = 0; h < 2; h++) {
                    float2 pd = *(const float2*)&g_P[(size_t)didx[2*mt+h] * 128 + 64 + col];
                    c3[mt][nt][2*h]   = pd.x;
                    c3[mt][nt][2*h+1] = pd.y;
                }
            }
        #pragma unroll
        for (int ch = 0; ch < 4; ch++) {
            // --- L2 chunk: em_c(32x32) = relu(be2_c + h1 @ We2_c) ---
            float c2[2][4][4];
            #pragma unroll
            for (int nt = 0; nt < 4; nt++) {
                float2 b = *(const float2*)&be2s[32*ch + 8*nt + 2*q];
                #pragma unroll
                for (int mt = 0; mt < 2; mt++) {
                    c2[mt][nt][0] = b.x; c2[mt][nt][1] = b.y;
                    c2[mt][nt][2] = b.x; c2[mt][nt][3] = b.y;
                }
            }
            #pragma unroll
            for (int kt = 0; kt < 4; kt++) {
                uint32_t a[2][4];
                #pragma unroll
                for (int mt = 0; mt < 2; mt++) {
                    int r0 = (g + 16*mt) * 36, r1 = (g + 8 + 16*mt) * 36;
                    a[mt][0] = h1s[r0 + 8*kt + q];
                    a[mt][1] = h1s[r1 + 8*kt + q];
                    a[mt][2] = h1s[r0 + 8*kt + q + 4];
                    a[mt][3] = h1s[r1 + 8*kt + q + 4];
                }
                #pragma unroll
                for (int nt = 0; nt < 4; nt++) {
                    uint32_t b0 = W2s[(32*ch + 8*nt + g)*36 + 8*kt + q];
                    uint32_t b1 = W2s[(32*ch + 8*nt + g)*36 + 8*kt + q + 4];
                    mma8(c2[0][nt], a[0][0],a[0][1],a[0][2],a[0][3], b0, b1);
                    mma8(c2[1][nt], a[1][0],a[1][1],a[1][2],a[1][3], b0, b1);
                }
            }
            // --- convert em C-frags to A-frags in registers, feed L3 ---
            #pragma unroll
            for (int kt = 0; kt < 4; kt++) {
                uint32_t a[2][4];
                #pragma unroll
                for (int mt = 0; mt < 2; mt++)
                    frag_c2a(c2[mt][kt][0], c2[mt][kt][1], c2[mt][kt][2], c2[mt][kt][3],
                             lane, a[mt]);
                #pragma unroll
                for (int nt = 0; nt < 8; nt++) {
                    uint32_t b0 = W3s[(8*nt+g)*132 + 32*ch + 8*kt + q];
                    uint32_t b1 = W3s[(8*nt+g)*132 + 32*ch + 8*kt + q + 4];
                    mma8(c3[0][nt], a[0][0],a[0][1],a[0][2],a[0][3], b0, b1);
                    mma8(c3[1][nt], a[1][0],a[1][1],a[1][2],a[1][3], b0, b1);
                }
            }
        }

        // ---- h2 C-frags -> A-frags once (64 regs), reused by all n4 ------
        uint32_t h2a[8][2][4];
        #pragma unroll
        for (int kt = 0; kt < 8; kt++)
            #pragma unroll
            for (int mt = 0; mt < 2; mt++)
                frag_c2a(c3[mt][kt][0], c3[mt][kt][1], c3[mt][kt][2], c3[mt][kt][3],
                         lane, h2a[kt][mt]);

        // ============ L4: nm(32x128) = relu(bn2 + h2 @ Wn2), scatter ======
        #pragma unroll
        for (int n4 = 0; n4 < 4; n4++) {
            float c4[2][4][4];
            #pragma unroll
            for (int nt = 0; nt < 4; nt++) {
                float2 b = *(const float2*)&bn2s[32*n4 + 8*nt + 2*q];
                #pragma unroll
                for (int mt = 0; mt < 2; mt++) {
                    c4[mt][nt][0] = b.x; c4[mt][nt][1] = b.y;
                    c4[mt][nt][2] = b.x; c4[mt][nt][3] = b.y;
                }
            }
            #pragma unroll
            for (int kt = 0; kt < 8; kt++) {
                #pragma unroll
                for (int nt = 0; nt < 4; nt++) {
                    uint32_t b0 = W4s[(32*n4 + 8*nt + g)*68 + 8*kt + q];
                    uint32_t b1 = W4s[(32*n4 + 8*nt + g)*68 + 8*kt + q + 4];
                    mma8(c4[0][nt], h2a[kt][0][0],h2a[kt][0][1],h2a[kt][0][2],h2a[kt][0][3], b0, b1);
                    mma8(c4[1][nt], h2a[kt][1][0],h2a[kt][1][1],h2a[kt][1][2],h2a[kt][1][3], b0, b1);
                }
            }
            // direct scatter from C-fragments: cols (2q, 2q+1) adjacent
            #pragma unroll
            for (int mt = 0; mt < 2; mt++) {
                #pragma unroll
                for (int nt = 0; nt < 4; nt++) {
                    const int col = 32*n4 + 8*nt + 2*q;
                    if (val[2*mt])
                        red2(out + (size_t)didx[2*mt] * 128 + col,
                             fmaxf(c4[mt][nt][0], 0.f), fmaxf(c4[mt][nt][1], 0.f));
                    if (val[2*mt+1])
                        red2(out + (size_t)didx[2*mt+1] * 128 + col,
                             fmaxf(c4[mt][nt][2], 0.f), fmaxf(c4[mt][nt][3], 0.f));
                }
            }
        }
    }
}

// ---------------------------------------------------------------------------
extern "C" void kernel_launch(void* const* d_in, const int* in_sizes, int n_in,
                              void* d_out, int out_size) {
    const float* nf  = (const float*)d_in[0];
    const float* ef  = (const float*)d_in[1];
    const int*   ei  = (const int*)  d_in[2];
    const float* We1 = (const float*)d_in[3];
    const float* be1 = (const float*)d_in[4];
    const float* We2 = (const float*)d_in[5];
    const float* be2 = (const float*)d_in[6];
    const float* Wn1 = (const float*)d_in[7];
    const float* bn1 = (const float*)d_in[8];
    const float* Wn2 = (const float*)d_in[9];
    const float* bn2 = (const float*)d_in[10];
    float* out = (float*)d_out;

    const int Nn = in_sizes[0] / 128;
    const int E  = in_sizes[2] / 2;
    const int ntiles = (E + TILE_E - 1) / TILE_E;

    precompute_kernel<<<(Nn + 15) / 16, 128>>>(nf, We1, be1, Wn1, bn1, out, Nn);

    cudaFuncSetAttribute(edge_mma_kernel,
                         cudaFuncAttributeMaxDynamicSharedMemorySize, SM_TOTAL);
    edge_mma_kernel<<<152, TPB, SM_TOTAL>>>(ef, ei, We1, We2, be2,
                                            Wn1, Wn2, bn2, out, E, ntiles);
}

// round 6
// speedup vs baseline: 4.2739x; 1.1421x over previous
#include <cuda_runtime.h>
#include <cstdint>

#define TPB 384
#define NWARP 12
#define TILE_E (NWARP * 32)
#define MAXN 50000

typedef unsigned long long u64;

// Per-node precomputed projections, COLUMN-PERMUTED for float4 fragment loads:
// slice0 [0:32)  = nf@We1[0:128]+be1 (src),  perm: q*8  + nt*2 + b  (col=8nt+2q+b)
// slice1 [32:64) = nf@We1[128:256]   (dst),  same perm within slice
// slice2 [64:128)= nf@Wn1[0:128]+bn1 (pre2), perm: q*16 + nt*2 + b
__device__ __align__(16) float g_P[MAXN * 128];

// ------------------------------- helpers ----------------------------------
__device__ __forceinline__ uint32_t f2tf(float f) {   // RNA round to tf32
    uint32_t r; asm("cvt.rna.tf32.f32 %0, %1;" : "=r"(r) : "f"(f)); return r;
}
__device__ __forceinline__ void red4(float* p, float a, float b, float c, float d) {
    asm volatile("red.global.add.v4.f32 [%0], {%1,%2,%3,%4};"
                 :: "l"(p), "f"(a), "f"(b), "f"(c), "f"(d) : "memory");
}
__device__ __forceinline__ u64 pk2(float lo, float hi) {
    u64 r;
    asm("mov.b64 %0, {%1, %2};" : "=l"(r)
        : "r"(__float_as_uint(lo)), "r"(__float_as_uint(hi)));
    return r;
}
__device__ __forceinline__ float2 up2(u64 v) {
    unsigned lo, hi;
    asm("mov.b64 {%0, %1}, %2;" : "=r"(lo), "=r"(hi) : "l"(v));
    return make_float2(__uint_as_float(lo), __uint_as_float(hi));
}
__device__ __forceinline__ u64 fma2(u64 a, u64 b, u64 c) {
    u64 d;
    asm("fma.rn.f32x2 %0, %1, %2, %3;" : "=l"(d) : "l"(a), "l"(b), "l"(c));
    return d;
}
// D(16x8,f32) += A(16x8,tf32) @ B(8x8,tf32)
__device__ __forceinline__ void mma8(float* c, uint32_t a0, uint32_t a1,
                                     uint32_t a2, uint32_t a3,
                                     uint32_t b0, uint32_t b1) {
    asm volatile("mma.sync.aligned.m16n8k8.row.col.f32.tf32.tf32.f32 "
                 "{%0,%1,%2,%3}, {%4,%5,%6,%7}, {%8,%9}, {%0,%1,%2,%3};"
                 : "+f"(c[0]), "+f"(c[1]), "+f"(c[2]), "+f"(c[3])
                 : "r"(a0), "r"(a1), "r"(a2), "r"(a3), "r"(b0), "r"(b1));
}
// C-fragment (16x8) -> A-fragment of same tile (relu + tf32), register shuffles
__device__ __forceinline__ void frag_c2a(float c0, float c1, float c2, float c3,
                                         int lane, uint32_t a[4]) {
    const unsigned F = 0xFFFFFFFFu;
    uint32_t r0 = f2tf(fmaxf(c0, 0.f)), r1 = f2tf(fmaxf(c1, 0.f));
    uint32_t r2 = f2tf(fmaxf(c2, 0.f)), r3 = f2tf(fmaxf(c3, 0.f));
    int l1 = (lane & 28) | ((lane & 3) >> 1);
    int l2 = l1 + 2;
    bool odd = lane & 1;
    uint32_t s0 = __shfl_sync(F, r0, l1), s1 = __shfl_sync(F, r1, l1);
    uint32_t s2 = __shfl_sync(F, r2, l1), s3 = __shfl_sync(F, r3, l1);
    uint32_t t0 = __shfl_sync(F, r0, l2), t1 = __shfl_sync(F, r1, l2);
    uint32_t t2 = __shfl_sync(F, r2, l2), t3 = __shfl_sync(F, r3, l2);
    a[0] = odd ? s1 : s0;  a[1] = odd ? s3 : s2;
    a[2] = odd ? t1 : t0;  a[3] = odd ? t3 : t2;
}
// column permutation for g_P storage
__device__ __forceinline__ int permP(int j) {
    if (j < 64) {
        int s = j & 32, c = j & 31;
        return s + ((c >> 1) & 3) * 8 + (c >> 3) * 2 + (c & 1);
    }
    int c = j - 64;
    return 64 + ((c >> 1) & 3) * 16 + (c >> 3) * 2 + (c & 1);
}

// ---------------------------------------------------------------------------
// Precompute: 16 nodes/block, packed f32x2 over k-pairs (exact fp32).
// Stores permuted columns; also initializes out = node_features.
// ---------------------------------------------------------------------------
__global__ void __launch_bounds__(128) precompute_kernel(
    const float* __restrict__ nf,
    const float* __restrict__ We1,
    const float* __restrict__ be1,
    const float* __restrict__ Wn1,
    const float* __restrict__ bn1,
    float* __restrict__ out, int Nn)
{
    __shared__ float nfs[16][128];
    const int nb  = blockIdx.x * 16;
    const int tid = threadIdx.x;

    #pragma unroll
    for (int i = 0; i < 16; i++) {
        int n = nb + i;
        if (n < Nn) {
            float v = nf[n * 128 + tid];
            nfs[i][tid] = v;
            out[n * 128 + tid] = v;
        } else nfs[i][tid] = 0.f;
    }
    __syncthreads();

    const int j = tid;
    const float* wcol; int stride; float bias;
    if (j < 32)      { wcol = We1 + j;                 stride = 32; bias = be1[j]; }
    else if (j < 64) { wcol = We1 + 128 * 32 + (j-32); stride = 32; bias = 0.f; }
    else             { wcol = Wn1 + (j - 64);          stride = 64; bias = bn1[j-64]; }

    u64 acc2[16];
    #pragma unroll
    for (int i = 0; i < 16; i++) acc2[i] = pk2(bias, 0.f);

    #pragma unroll 2
    for (int k = 0; k < 128; k += 2) {
        u64 w2 = pk2(wcol[k * stride], wcol[(k + 1) * stride]);
        #pragma unroll
        for (int i = 0; i < 16; i++) {
            float2 v = *(const float2*)&nfs[i][k];
            acc2[i] = fma2(pk2(v.x, v.y), w2, acc2[i]);
        }
    }
    const int pj = permP(j);
    #pragma unroll
    for (int i = 0; i < 16; i++) {
        int n = nb + i;
        if (n < Nn) {
            float2 f = up2(acc2[i]);
            g_P[n * 128 + pj] = f.x + f.y;
        }
    }
}

// ---------------------------------------------------------------------------
// Edge kernel: persistent, 12 independent warps x 32 edges, mma.sync tf32.
// ef staged via smem (coalesced); P loaded as float4 (permuted layout);
// scatter staged via smem -> row-coalesced red4.
// ---------------------------------------------------------------------------
#define OFF_W1  0            // [32][68]  -> 8704
#define OFF_W2  8704         // [128][36] -> 18432
#define OFF_W3  27136        // [64][132] -> 33792
#define OFF_W4  60928        // [128][68] -> 34816
#define OFF_BE2 95744
#define OFF_BN2 96256
#define OFF_SCR 96768
#define WS_BYTES 4608        // per-warp buffer [32][36] words (ef / h1 / nm phases)
#define SM_TOTAL (OFF_SCR + NWARP * WS_BYTES)   // 152064

__global__ void __launch_bounds__(TPB, 1) edge_mma_kernel(
    const float* __restrict__ ef,
    const int*   __restrict__ eidx,
    const float* __restrict__ We1,
    const float* __restrict__ We2,
    const float* __restrict__ be2,
    const float* __restrict__ Wn1,
    const float* __restrict__ Wn2,
    const float* __restrict__ bn2,
    float* __restrict__ out, int E, int ntiles)
{
    extern __shared__ char sm[];
    uint32_t* W1s = (uint32_t*)(sm + OFF_W1);
    uint32_t* W2s = (uint32_t*)(sm + OFF_W2);
    uint32_t* W3s = (uint32_t*)(sm + OFF_W3);
    uint32_t* W4s = (uint32_t*)(sm + OFF_W4);
    float* be2s = (float*)(sm + OFF_BE2);
    float* bn2s = (float*)(sm + OFF_BN2);

    const int tid = threadIdx.x;
    for (int i = tid; i < 32 * 64;  i += TPB) { int n = i >> 6, k = i & 63;  W1s[n*68  + k] = f2tf(We1[(256 + k) * 32 + n]); }
    for (int i = tid; i < 128 * 32; i += TPB) { int n = i >> 5, k = i & 31;  W2s[n*36  + k] = f2tf(We2[k * 128 + n]); }
    for (int i = tid; i < 64 * 128; i += TPB) { int n = i >> 7, k = i & 127; W3s[n*132 + k] = f2tf(Wn1[(128 + k) * 64 + n]); }
    for (int i = tid; i < 128 * 64; i += TPB) { int n = i >> 6, k = i & 63;  W4s[n*68  + k] = f2tf(Wn2[k * 128 + n]); }
    if (tid < 128) { be2s[tid] = be2[tid]; bn2s[tid] = bn2[tid]; }
    __syncthreads();

    const int lane = tid & 31, wid = tid >> 5;
    const int g = lane >> 2, q = lane & 3;
    const unsigned F = 0xFFFFFFFFu;
    uint32_t* buf  = (uint32_t*)(sm + OFF_SCR + wid * WS_BYTES);  // [32][36]
    float*    buff = (float*)buf;

    for (int t = blockIdx.x; t < ntiles; t += gridDim.x) {
        const int eb = t * TILE_E + wid * 32;

        // rows m = 2*mt + h  ->  warp-local rows {g, g+8, g+16, g+24}
        int er[4], sidx[4], didx[4];
        #pragma unroll
        for (int m = 0; m < 4; m++) {
            int r = eb + g + ((m >> 1) << 4) + ((m & 1) << 3);
            er[m]  = (r < E) ? r : (E - 1);
            sidx[m] = eidx[er[m]];
            didx[m] = eidx[E + er[m]];
        }
        // this lane's own edge (for scatter dst broadcast)
        const int rl = eb + lane;
        const int dl = eidx[E + ((rl < E) ? rl : (E - 1))];

        // ======== L1 init: c1 = pre1 (float4 loads from permuted P) =======
        float c1[2][4][4];
        #pragma unroll
        for (int m = 0; m < 4; m++) {
            const int mt = m >> 1, h = m & 1;
            float4 u0 = *(const float4*)&g_P[(size_t)sidx[m] * 128 + q * 8];
            float4 u1 = *(const float4*)&g_P[(size_t)sidx[m] * 128 + q * 8 + 4];
            float4 v0 = *(const float4*)&g_P[(size_t)didx[m] * 128 + 32 + q * 8];
            float4 v1 = *(const float4*)&g_P[(size_t)didx[m] * 128 + 32 + q * 8 + 4];
            c1[mt][0][2*h] = u0.x + v0.x;  c1[mt][0][2*h+1] = u0.y + v0.y;
            c1[mt][1][2*h] = u0.z + v0.z;  c1[mt][1][2*h+1] = u0.w + v0.w;
            c1[mt][2][2*h] = u1.x + v1.x;  c1[mt][2][2*h+1] = u1.y + v1.y;
            c1[mt][3][2*h] = u1.z + v1.z;  c1[mt][3][2*h+1] = u1.w + v1.w;
        }

        // ======== L1 mainloop: stage ef half -> mma (2 halves) ============
        #pragma unroll
        for (int hf = 0; hf < 2; hf++) {
            __syncwarp();
            #pragma unroll
            for (int i = 0; i < 8; i++) {
                int row = 4 * i + (lane >> 3);
                int r = eb + row; r = (r < E) ? r : (E - 1);
                float4 v = *(const float4*)&ef[(size_t)r * 64 + hf * 32 + 4 * (lane & 7)];
                uint4 w = { f2tf(v.x), f2tf(v.y), f2tf(v.z), f2tf(v.w) };
                *(uint4*)&buf[row * 36 + 4 * (lane & 7)] = w;
            }
            __syncwarp();
            #pragma unroll
            for (int kt = 0; kt < 4; kt++) {
                uint32_t a[2][4];
                #pragma unroll
                for (int mt = 0; mt < 2; mt++) {
                    int r0 = (g + 16*mt) * 36, r1 = (g + 8 + 16*mt) * 36;
                    a[mt][0] = buf[r0 + 8*kt + q];
                    a[mt][1] = buf[r1 + 8*kt + q];
                    a[mt][2] = buf[r0 + 8*kt + q + 4];
                    a[mt][3] = buf[r1 + 8*kt + q + 4];
                }
                const int ktg = 4 * hf + kt;
                #pragma unroll
                for (int nt = 0; nt < 4; nt++) {
                    uint32_t b0 = W1s[(8*nt+g)*68 + 8*ktg + q];
                    uint32_t b1 = W1s[(8*nt+g)*68 + 8*ktg + q + 4];
                    mma8(c1[0][nt], a[0][0],a[0][1],a[0][2],a[0][3], b0, b1);
                    mma8(c1[1][nt], a[1][0],a[1][1],a[1][2],a[1][3], b0, b1);
                }
            }
        }
        // h1 -> buf (relu + tf32), reused across 4 K-chunks of L2
        __syncwarp();
        #pragma unroll
        for (int mt = 0; mt < 2; mt++)
            #pragma unroll
            for (int nt = 0; nt < 4; nt++) {
                const int col = 8 * nt + 2 * q;
                uint2 v0 = { f2tf(fmaxf(c1[mt][nt][0], 0.f)), f2tf(fmaxf(c1[mt][nt][1], 0.f)) };
                uint2 v1 = { f2tf(fmaxf(c1[mt][nt][2], 0.f)), f2tf(fmaxf(c1[mt][nt][3], 0.f)) };
                *(uint2*)&buf[(g + 16*mt) * 36 + col]     = v0;
                *(uint2*)&buf[(g + 8 + 16*mt) * 36 + col] = v1;
            }
        __syncwarp();

        // ========== L2+L3 fused: h2(32x64) = relu(pre2 + em @ Wn1m) =======
        float c3[2][8][4];
        #pragma unroll
        for (int m = 0; m < 4; m++) {
            const int mt = m >> 1, h = m & 1;
            const float* Pp = &g_P[(size_t)didx[m] * 128 + 64 + q * 16];
            #pragma unroll
            for (int w = 0; w < 4; w++) {
                float4 v = *(const float4*)(Pp + 4 * w);
                c3[mt][2*w][2*h]     = v.x;  c3[mt][2*w][2*h+1]   = v.y;
                c3[mt][2*w+1][2*h]   = v.z;  c3[mt][2*w+1][2*h+1] = v.w;
            }
        }
        #pragma unroll
        for (int ch = 0; ch < 4; ch++) {
            // --- L2 chunk: em_c(32x32) = relu(be2_c + h1 @ We2_c) ---
            float c2[2][4][4];
            #pragma unroll
            for (int nt = 0; nt < 4; nt++) {
                float2 b = *(const float2*)&be2s[32*ch + 8*nt + 2*q];
                #pragma unroll
                for (int mt = 0; mt < 2; mt++) {
                    c2[mt][nt][0] = b.x; c2[mt][nt][1] = b.y;
                    c2[mt][nt][2] = b.x; c2[mt][nt][3] = b.y;
                }
            }
            #pragma unroll
            for (int kt = 0; kt < 4; kt++) {
                uint32_t a[2][4];
                #pragma unroll
                for (int mt = 0; mt < 2; mt++) {
                    int r0 = (g + 16*mt) * 36, r1 = (g + 8 + 16*mt) * 36;
                    a[mt][0] = buf[r0 + 8*kt + q];
                    a[mt][1] = buf[r1 + 8*kt + q];
                    a[mt][2] = buf[r0 + 8*kt + q + 4];
                    a[mt][3] = buf[r1 + 8*kt + q + 4];
                }
                #pragma unroll
                for (int nt = 0; nt < 4; nt++) {
                    uint32_t b0 = W2s[(32*ch + 8*nt + g)*36 + 8*kt + q];
                    uint32_t b1 = W2s[(32*ch + 8*nt + g)*36 + 8*kt + q + 4];
                    mma8(c2[0][nt], a[0][0],a[0][1],a[0][2],a[0][3], b0, b1);
                    mma8(c2[1][nt], a[1][0],a[1][1],a[1][2],a[1][3], b0, b1);
                }
            }
            // --- convert em C-frags to A-frags in registers, feed L3 ---
            #pragma unroll
            for (int kt = 0; kt < 4; kt++) {
                uint32_t a[2][4];
                #pragma unroll
                for (int mt = 0; mt < 2; mt++)
                    frag_c2a(c2[mt][kt][0], c2[mt][kt][1], c2[mt][kt][2], c2[mt][kt][3],
                             lane, a[mt]);
                #pragma unroll
                for (int nt = 0; nt < 8; nt++) {
                    uint32_t b0 = W3s[(8*nt+g)*132 + 32*ch + 8*kt + q];
                    uint32_t b1 = W3s[(8*nt+g)*132 + 32*ch + 8*kt + q + 4];
                    mma8(c3[0][nt], a[0][0],a[0][1],a[0][2],a[0][3], b0, b1);
                    mma8(c3[1][nt], a[1][0],a[1][1],a[1][2],a[1][3], b0, b1);
                }
            }
        }

        // ---- h2 C-frags -> A-frags once (64 regs), reused by all n4 ------
        uint32_t h2a[8][2][4];
        #pragma unroll
        for (int kt = 0; kt < 8; kt++)
            #pragma unroll
            for (int mt = 0; mt < 2; mt++)
                frag_c2a(c3[mt][kt][0], c3[mt][kt][1], c3[mt][kt][2], c3[mt][kt][3],
                         lane, h2a[kt][mt]);

        // ============ L4: nm(32x128) = relu(bn2 + h2 @ Wn2), scatter ======
        #pragma unroll
        for (int n4 = 0; n4 < 4; n4++) {
            float c4[2][4][4];
            #pragma unroll
            for (int nt = 0; nt < 4; nt++) {
                float2 b = *(const float2*)&bn2s[32*n4 + 8*nt + 2*q];
                #pragma unroll
                for (int mt = 0; mt < 2; mt++) {
                    c4[mt][nt][0] = b.x; c4[mt][nt][1] = b.y;
                    c4[mt][nt][2] = b.x; c4[mt][nt][3] = b.y;
                }
            }
            #pragma unroll
            for (int kt = 0; kt < 8; kt++) {
                #pragma unroll
                for (int nt = 0; nt < 4; nt++) {
                    uint32_t b0 = W4s[(32*n4 + 8*nt + g)*68 + 8*kt + q];
                    uint32_t b1 = W4s[(32*n4 + 8*nt + g)*68 + 8*kt + q + 4];
                    mma8(c4[0][nt], h2a[kt][0][0],h2a[kt][0][1],h2a[kt][0][2],h2a[kt][0][3], b0, b1);
                    mma8(c4[1][nt], h2a[kt][1][0],h2a[kt][1][1],h2a[kt][1][2],h2a[kt][1][3], b0, b1);
                }
            }
            // transpose through smem -> row-coalesced red4
            __syncwarp();
            #pragma unroll
            for (int mt = 0; mt < 2; mt++)
                #pragma unroll
                for (int nt = 0; nt < 4; nt++) {
                    const int col = 8 * nt + 2 * q;
                    float2 v0 = { fmaxf(c4[mt][nt][0], 0.f), fmaxf(c4[mt][nt][1], 0.f) };
                    float2 v1 = { fmaxf(c4[mt][nt][2], 0.f), fmaxf(c4[mt][nt][3], 0.f) };
                    *(float2*)&buff[(g + 16*mt) * 36 + col]     = v0;
                    *(float2*)&buff[(g + 8 + 16*mt) * 36 + col] = v1;
                }
            __syncwarp();
            #pragma unroll
            for (int i = 0; i < 8; i++) {
                int row = 4 * i + (lane >> 3);
                float4 v = *(const float4*)&buff[row * 36 + 4 * (lane & 7)];
                int dr = __shfl_sync(F, dl, row);
                if (eb + row < E)
                    red4(out + (size_t)dr * 128 + 32 * n4 + 4 * (lane & 7),
                         v.x, v.y, v.z, v.w);
            }
        }
    }
}

// ---------------------------------------------------------------------------
extern "C" void kernel_launch(void* const* d_in, const int* in_sizes, int n_in,
                              void* d_out, int out_size) {
    const float* nf  = (const float*)d_in[0];
    const float* ef  = (const float*)d_in[1];
    const int*   ei  = (const int*)  d_in[2];
    const float* We1 = (const float*)d_in[3];
    const float* be1 = (const float*)d_in[4];
    const float* We2 = (const float*)d_in[5];
    const float* be2 = (const float*)d_in[6];
    const float* Wn1 = (const float*)d_in[7];
    const float* bn1 = (const float*)d_in[8];
    const float* Wn2 = (const float*)d_in[9];
    const float* bn2 = (const float*)d_in[10];
    float* out = (float*)d_out;

    const int Nn = in_sizes[0] / 128;
    const int E  = in_sizes[2] / 2;
    const int ntiles = (E + TILE_E - 1) / TILE_E;

    precompute_kernel<<<(Nn + 15) / 16, 128>>>(nf, We1, be1, Wn1, bn1, out, Nn);

    cudaFuncSetAttribute(edge_mma_kernel,
                         cudaFuncAttributeMaxDynamicSharedMemorySize, SM_TOTAL);
    edge_mma_kernel<<<152, TPB, SM_TOTAL>>>(ef, ei, We1, We2, be2,
                                            Wn1, Wn2, bn2, out, E, ntiles);
}